// round 6
// baseline (speedup 1.0000x reference)
#include <cuda_runtime.h>
#include <math.h>

#define T_ 6
#define N_ 20000
#define E_ 400000
#define F_ 64
#define C_ 64
#define H_ 128
#define BIG_ 0x3fffffff
#define KP_ 72   // padded feature channels: 64 x + 2 labels + zeros
#define KU_ 66   // used channels (ch 66..71 identically zero)

// ---------------- scratch (device globals; no allocation) ----------------
__device__ __align__(128) int   g_lvl[T_][N_];
__device__ __align__(128) int   g_count[T_][N_];
__device__ __align__(128) int   g_rowptr[T_][N_ + 1];
__device__ __align__(128) int   g_cursor[T_][N_];
__device__ __align__(128) int   g_csrsrc[T_][E_];
__device__ __align__(128) float g_dinv[T_][N_];
__device__ __align__(128) float g_dxl[T_][N_ * KP_];  // dinv[n]*[x,labels,0pad]
__device__ __align__(128) float g_col[T_][N_];        // dinv*(h1 . W2[:,127])
__device__ unsigned long long   g_argmax[T_];
__device__ __align__(128) float g_seq[T_ * H_];

// ---------------- reset + seed fused (membership test in smem) ----------------
__global__ void k_reset(const int* __restrict__ tgt) {
    int t = blockIdx.y;
    __shared__ int stgt[C_];
    if (threadIdx.x < C_) stgt[threadIdx.x] = tgt[t * C_ + threadIdx.x];
    __syncthreads();
    int i4 = (blockIdx.x * 256 + threadIdx.x) * 4;
    if (i4 < N_) {
        int4 v = make_int4(BIG_, BIG_, BIG_, BIG_);
#pragma unroll
        for (int j = 0; j < C_; j++) {
            int tg = stgt[j];
            if (tg == i4) v.x = 0;
            if (tg == i4 + 1) v.y = 0;
            if (tg == i4 + 2) v.z = 0;
            if (tg == i4 + 3) v.w = 0;
        }
        *(int4*)&g_lvl[t][i4] = v;
        *(int4*)&g_count[t][i4] = make_int4(0, 0, 0, 0);
    }
    if (blockIdx.x == 0 && threadIdx.x == 0) g_argmax[t] = 0ULL;
}

// Level-stamped BFS iteration k, 4 edges per thread for MLP.
__global__ void k_prop(const int* __restrict__ ei, int k) {
    int t = blockIdx.y;
    int i = (blockIdx.x * 256 + threadIdx.x) * 4;
    if (i >= E_) return;
    const int* src = ei + (size_t)t * 2 * E_;
    const int* dst = src + E_;
    int4 s4 = *(const int4*)&src[i];
    int4 d4 = *(const int4*)&dst[i];
    int* lvl = g_lvl[t];
    int ls0 = lvl[s4.x], ls1 = lvl[s4.y], ls2 = lvl[s4.z], ls3 = lvl[s4.w];
    int ld0 = lvl[d4.x], ld1 = lvl[d4.y], ld2 = lvl[d4.z], ld3 = lvl[d4.w];
    if (ls0 < k && ld0 > k) atomicMin(&lvl[d4.x], k);
    if (ld0 < k && ls0 > k) atomicMin(&lvl[s4.x], k);
    if (ls1 < k && ld1 > k) atomicMin(&lvl[d4.y], k);
    if (ld1 < k && ls1 > k) atomicMin(&lvl[s4.y], k);
    if (ls2 < k && ld2 > k) atomicMin(&lvl[d4.z], k);
    if (ld2 < k && ls2 > k) atomicMin(&lvl[s4.z], k);
    if (ls3 < k && ld3 > k) atomicMin(&lvl[d4.w], k);
    if (ld3 < k && ls3 > k) atomicMin(&lvl[s4.w], k);
}

__global__ void k_count(const int* __restrict__ ei) {
    int t = blockIdx.y;
    int i = (blockIdx.x * 256 + threadIdx.x) * 4;
    if (i >= E_) return;
    const int* src = ei + (size_t)t * 2 * E_;
    const int* dst = src + E_;
    int4 s4 = *(const int4*)&src[i];
    int4 d4 = *(const int4*)&dst[i];
    const int* lvl = g_lvl[t];
    int ls0 = lvl[s4.x], ls1 = lvl[s4.y], ls2 = lvl[s4.z], ls3 = lvl[s4.w];
    int ld0 = lvl[d4.x], ld1 = lvl[d4.y], ld2 = lvl[d4.z], ld3 = lvl[d4.w];
    if (ls0 < BIG_ && ld0 < BIG_) atomicAdd(&g_count[t][d4.x], 1);
    if (ls1 < BIG_ && ld1 < BIG_) atomicAdd(&g_count[t][d4.y], 1);
    if (ls2 < BIG_ && ld2 < BIG_) atomicAdd(&g_count[t][d4.z], 1);
    if (ls3 < BIG_ && ld3 < BIG_) atomicAdd(&g_count[t][d4.w], 1);
}

__global__ void k_scan() {
    int t = blockIdx.x;
    const int CH = 20;
    __shared__ int s[1024];
    int tid = threadIdx.x;
    int base = tid * CH;
    int loc[CH];
    int sum = 0;
#pragma unroll
    for (int i = 0; i < CH; i++) {
        int idx = base + i;
        int c = (idx < N_) ? g_count[t][idx] : 0;
        loc[i] = sum;
        sum += c;
    }
    s[tid] = sum;
    __syncthreads();
    for (int off = 1; off < 1024; off <<= 1) {
        int v = (tid >= off) ? s[tid - off] : 0;
        __syncthreads();
        s[tid] += v;
        __syncthreads();
    }
    int excl = s[tid] - sum;
#pragma unroll
    for (int i = 0; i < CH; i++) {
        int idx = base + i;
        if (idx < N_) {
            int o = excl + loc[i];
            g_rowptr[t][idx] = o;
            g_cursor[t][idx] = o;
            int lv = g_lvl[t][idx];
            g_dinv[t][idx] = (lv < BIG_) ? rsqrtf((float)g_count[t][idx] + 1.0f) : 0.0f;
        }
    }
    if (tid == 1023) g_rowptr[t][N_] = s[1023];
}

// ---------------- fill (CSR) + scale (dxl) fused via block-range split ----------------
#define FB_ ((E_ / 4 + 255) / 256)                 // 391 fill blocks
#define SB_ ((N_ * (KP_ / 4) + 255) / 256)         // scale blocks
__global__ void __launch_bounds__(256) k_fillscale(const int* __restrict__ ei,
                                                   const float* __restrict__ x) {
    int t = blockIdx.y;
    if (blockIdx.x < FB_) {
        int i = (blockIdx.x * 256 + threadIdx.x) * 4;
        if (i >= E_) return;
        const int* src = ei + (size_t)t * 2 * E_;
        const int* dst = src + E_;
        int4 s4 = *(const int4*)&src[i];
        int4 d4 = *(const int4*)&dst[i];
        const int* lvl = g_lvl[t];
        int ls0 = lvl[s4.x], ls1 = lvl[s4.y], ls2 = lvl[s4.z], ls3 = lvl[s4.w];
        int ld0 = lvl[d4.x], ld1 = lvl[d4.y], ld2 = lvl[d4.z], ld3 = lvl[d4.w];
        if (ls0 < BIG_ && ld0 < BIG_) g_csrsrc[t][atomicAdd(&g_cursor[t][d4.x], 1)] = s4.x;
        if (ls1 < BIG_ && ld1 < BIG_) g_csrsrc[t][atomicAdd(&g_cursor[t][d4.y], 1)] = s4.y;
        if (ls2 < BIG_ && ld2 < BIG_) g_csrsrc[t][atomicAdd(&g_cursor[t][d4.z], 1)] = s4.z;
        if (ls3 < BIG_ && ld3 < BIG_) g_csrsrc[t][atomicAdd(&g_cursor[t][d4.w], 1)] = s4.w;
    } else {
        int e = (blockIdx.x - FB_) * 256 + threadIdx.x;
        const int NQ = KP_ / 4;  // 18 quads per node
        if (e >= N_ * NQ) return;
        int n = e / NQ;
        int q = e - n * NQ;
        float d = g_dinv[t][n];
        float4 v;
        if (q < 16) {
            float4 xv = *(const float4*)&x[((size_t)t * N_ + n) * F_ + q * 4];
            v = make_float4(d * xv.x, d * xv.y, d * xv.z, d * xv.w);
        } else if (q == 16) {
            int lv = g_lvl[t][n];
            v = make_float4(d * (lv == 0 ? 1.f : 0.f),
                            d * ((lv > 0 && lv < BIG_) ? 1.f : 0.f), 0.f, 0.f);
        } else {
            v = make_float4(0.f, 0.f, 0.f, 0.f);
        }
        *(float4*)&g_dxl[t][(size_t)n * KP_ + q * 4] = v;
    }
}

__device__ __forceinline__ float warp_sum(float v) {
    v += __shfl_down_sync(0xffffffffu, v, 16);
    v += __shfl_down_sync(0xffffffffu, v, 8);
    v += __shfl_down_sync(0xffffffffu, v, 4);
    v += __shfl_down_sync(0xffffffffu, v, 2);
    v += __shfl_down_sync(0xffffffffu, v, 1);
    return v;
}

// ---------------- fused aggregate + GEMM + g_col epilogue ----------------
// Phase 1: warp w gathers rows m0+w*8..+7 of y = dinv*(sum dxl[src] + dxl[self])
//          directly into smem A-tile (row-major, stride 76 for 16B-aligned STS128).
// Phase 2: h1 = relu(y@W1 + b1) in regs; epilogue reduces g_col = dinv*(h1 . W2[:,127]).
#define BM 64
#define ASTRIDE 76
__global__ void __launch_bounds__(256) k_aggemm(const float* __restrict__ W1,
                                                const float* __restrict__ b1,
                                                const float* __restrict__ W2) {
    extern __shared__ float sm[];
    float* As = sm;                        // [64][76]
    float* Bs = As + BM * ASTRIDE;         // [66][128]
    float* w2cs = Bs + KU_ * H_;           // [128]
    float* b1s = w2cs + H_;                // [128]

    int t = blockIdx.y;
    int tid = threadIdx.x;
    int warp = tid >> 5, lane = tid & 31;
    int m0 = blockIdx.x * BM;
    const float* __restrict__ dxl = g_dxl[t];
    const int* __restrict__ csr = g_csrsrc[t];

    // cooperative loads of W1 (66x128), w2 col, b1
    for (int e = tid; e < KU_ * (H_ / 4); e += 256) {
        int kr = e >> 5;
        int cq = (e & 31) * 4;
        *(float4*)&Bs[kr * H_ + cq] = *(const float4*)&W1[(size_t)kr * H_ + cq];
    }
    if (tid < H_) {
        w2cs[tid] = W2[(size_t)tid * H_ + (H_ - 1)];
        b1s[tid] = b1[tid];
    }

    // Phase 1: gather 8 rows per warp
    bool ld = lane < (KP_ / 4);  // 18 lanes do float4 channel loads
    int co = lane * 4;
#pragma unroll
    for (int rr = 0; rr < 8; rr++) {
        int r = warp * 8 + rr;
        int row = m0 + r;
        float4 a = make_float4(0.f, 0.f, 0.f, 0.f);
        float4 a2 = make_float4(0.f, 0.f, 0.f, 0.f);
        if (row < N_) {
            int s0 = g_rowptr[t][row], s1 = g_rowptr[t][row + 1];
            if (ld) a = *(const float4*)&dxl[(size_t)row * KP_ + co];  // self
            int j = s0;
            for (; j + 2 <= s1; j += 2) {
                int u0 = csr[j], u1 = csr[j + 1];
                if (ld) {
                    float4 v0 = *(const float4*)&dxl[(size_t)u0 * KP_ + co];
                    float4 v1 = *(const float4*)&dxl[(size_t)u1 * KP_ + co];
                    a.x += v0.x; a.y += v0.y; a.z += v0.z; a.w += v0.w;
                    a2.x += v1.x; a2.y += v1.y; a2.z += v1.z; a2.w += v1.w;
                }
            }
            if (j < s1) {
                int u = csr[j];
                if (ld) {
                    float4 v = *(const float4*)&dxl[(size_t)u * KP_ + co];
                    a.x += v.x; a.y += v.y; a.z += v.z; a.w += v.w;
                }
            }
            float d = g_dinv[t][row];
            a.x = d * (a.x + a2.x); a.y = d * (a.y + a2.y);
            a.z = d * (a.z + a2.z); a.w = d * (a.w + a2.w);
        }
        if (ld) *(float4*)&As[r * ASTRIDE + co] = a;
    }
    __syncthreads();

    // Phase 2: GEMM. warp tr owns rows tr*8..+7; lane tc owns cols tc*4..+3
    int tc = lane, tr = warp;
    float acc[8][4];
#pragma unroll
    for (int i = 0; i < 8; i++)
#pragma unroll
        for (int j = 0; j < 4; j++) acc[i][j] = 0.0f;
#pragma unroll 2
    for (int k = 0; k < KU_; k++) {
        float4 b = *(float4*)&Bs[k * H_ + tc * 4];
#pragma unroll
        for (int i = 0; i < 8; i++) {
            float a = As[(tr * 8 + i) * ASTRIDE + k];  // warp-uniform
            acc[i][0] = fmaf(a, b.x, acc[i][0]);
            acc[i][1] = fmaf(a, b.y, acc[i][1]);
            acc[i][2] = fmaf(a, b.z, acc[i][2]);
            acc[i][3] = fmaf(a, b.w, acc[i][3]);
        }
    }

    float4 bb = *(float4*)&b1s[tc * 4];
    float w0 = w2cs[tc * 4], w1v = w2cs[tc * 4 + 1];
    float w2v = w2cs[tc * 4 + 2], w3 = w2cs[tc * 4 + 3];
#pragma unroll
    for (int i = 0; i < 8; i++) {
        int r = m0 + tr * 8 + i;
        if (r >= N_) break;
        float h0 = fmaxf(acc[i][0] + bb.x, 0.f);
        float h1 = fmaxf(acc[i][1] + bb.y, 0.f);
        float h2 = fmaxf(acc[i][2] + bb.z, 0.f);
        float h3 = fmaxf(acc[i][3] + bb.w, 0.f);
        float dot = h0 * w0 + h1 * w1v + h2 * w2v + h3 * w3;
        dot = warp_sum(dot);
        if (tc == 0) g_col[t][r] = g_dinv[t][r] * dot;
    }
}

// ---------------- layer-2 scalar aggregation + fused argmax ----------------
__global__ void __launch_bounds__(256) k_col_argmax(const float* __restrict__ b2) {
    int t = blockIdx.y;
    int tid = threadIdx.x;
    int warp = tid >> 5, lane = tid & 31;
    int row = blockIdx.x * 8 + warp;
    unsigned long long p = 0ULL;
    float b = b2[H_ - 1];
    if (row < N_) {
        int s0 = g_rowptr[t][row], s1 = g_rowptr[t][row + 1];
        const int* __restrict__ csr = g_csrsrc[t];
        const float* __restrict__ col = g_col[t];
        float s = 0.f;
        int j = s0 + lane;
        for (; j + 32 < s1; j += 64) s += col[csr[j]] + col[csr[j + 32]];
        if (j < s1) s += col[csr[j]];
        s = warp_sum(s);
        if (lane == 0) {
            float d = g_dinv[t][row];
            if (d > 0.f) {
                float v = fmaxf(fmaf(d, s + col[row], b), 0.f);
                p = ((unsigned long long)__float_as_uint(v) << 32) |
                    (unsigned int)(0x7fffffff - row);
            }
        }
    }
    __shared__ unsigned long long smx[8];
    if (lane == 0) smx[warp] = p;
    __syncthreads();
    if (tid == 0) {
        unsigned long long m = smx[0];
#pragma unroll
        for (int i = 1; i < 8; i++) m = (smx[i] > m) ? smx[i] : m;
        if (m) atomicMax(&g_argmax[t], m);
    }
}

// ---------------- recompute y on top's nbhd; h1; h2[top,:] -> g_seq ----------------
__global__ void __launch_bounds__(128) k_top(const float* __restrict__ W1,
                                             const float* __restrict__ b1,
                                             const float* __restrict__ W2,
                                             const float* __restrict__ b2) {
    int t = blockIdx.x;
    int top = 0x7fffffff - (int)(g_argmax[t] & 0x7fffffffULL);
    int c = threadIdx.x;
    __shared__ float yrow[KP_];
    __shared__ float svec[H_];
    const float* __restrict__ dxl = g_dxl[t];
    const int* __restrict__ csr = g_csrsrc[t];

    int s0 = g_rowptr[t][top], s1 = g_rowptr[t][top + 1];
    float sv = 0.f;
    float bc = b1[c];
    for (int idx = -1; idx < s1 - s0; idx++) {
        int u = (idx < 0) ? top : csr[s0 + idx];
        int u0 = g_rowptr[t][u], u1 = g_rowptr[t][u + 1];
        __syncthreads();
        if (c < KP_) {
            float a0 = dxl[(size_t)u * KP_ + c], a1 = 0.f, a2 = 0.f, a3 = 0.f;
            int j = u0;
            for (; j + 4 <= u1; j += 4) {
                a0 += dxl[(size_t)csr[j] * KP_ + c];
                a1 += dxl[(size_t)csr[j + 1] * KP_ + c];
                a2 += dxl[(size_t)csr[j + 2] * KP_ + c];
                a3 += dxl[(size_t)csr[j + 3] * KP_ + c];
            }
            for (; j < u1; j++) a0 += dxl[(size_t)csr[j] * KP_ + c];
            yrow[c] = g_dinv[t][u] * ((a0 + a1) + (a2 + a3));
        }
        __syncthreads();
        float h = bc;
#pragma unroll 2
        for (int k = 0; k < KU_; k++) h = fmaf(yrow[k], W1[(size_t)k * H_ + c], h);
        sv += g_dinv[t][u] * fmaxf(h, 0.f);
    }
    svec[c] = sv;
    __syncthreads();
    float o = 0.f;
#pragma unroll 4
    for (int k = 0; k < H_; k++) o = fmaf(svec[k], W2[(size_t)k * H_ + c], o);
    float dtop = g_dinv[t][top];
    g_seq[t * H_ + c] = fmaxf(fmaf(dtop, o, b2[c]), 0.f);
}

// ---------------- GRU + MLP head ----------------
__global__ void __launch_bounds__(128) k_final(const float* __restrict__ Wih,
                                               const float* __restrict__ Whh,
                                               const float* __restrict__ bih,
                                               const float* __restrict__ bhh,
                                               const float* __restrict__ Wc1,
                                               const float* __restrict__ bc1,
                                               const float* __restrict__ Wc2,
                                               const float* __restrict__ bc2,
                                               float* __restrict__ out) {
    __shared__ float h[H_], xt[H_], sgi[3 * H_], sgh[3 * H_], hid[H_ / 2];
    int tid = threadIdx.x, lane = tid & 31, w = tid >> 5;
    h[tid] = 0.0f;
    __syncthreads();
    for (int t = 0; t < T_; t++) {
        xt[tid] = g_seq[t * H_ + tid];
        __syncthreads();
        for (int o = w; o < 3 * H_; o += 4) {
            float si = 0.f, sh = 0.f;
            for (int k = lane; k < H_; k += 32) {
                si += xt[k] * Wih[(size_t)o * H_ + k];
                sh += h[k] * Whh[(size_t)o * H_ + k];
            }
            si = warp_sum(si);
            sh = warp_sum(sh);
            if (lane == 0) {
                sgi[o] = si + bih[o];
                sgh[o] = sh + bhh[o];
            }
        }
        __syncthreads();
        float r = 1.0f / (1.0f + expf(-(sgi[tid] + sgh[tid])));
        float z = 1.0f / (1.0f + expf(-(sgi[tid + H_] + sgh[tid + H_])));
        float n = tanhf(sgi[tid + 2 * H_] + r * sgh[tid + 2 * H_]);
        float hn = (1.0f - z) * n + z * h[tid];
        __syncthreads();
        h[tid] = hn;
        __syncthreads();
    }
    if (tid < H_ / 2) {
        float s = bc1[tid];
        for (int k = 0; k < H_; k++) s += h[k] * Wc1[(size_t)k * (H_ / 2) + tid];
        hid[tid] = fmaxf(s, 0.0f);
    }
    __syncthreads();
    if (tid == 0) {
        float s = bc2[0];
        for (int j = 0; j < H_ / 2; j++) s += hid[j] * Wc2[j];
        out[0] = 1.0f / (1.0f + expf(-s));
    }
}

// ---------------- launch ----------------
extern "C" void kernel_launch(void* const* d_in, const int* in_sizes, int n_in,
                              void* d_out, int out_size) {
    const float* x   = (const float*)d_in[0];
    const int*   ei  = (const int*)d_in[1];
    const int*   tgt = (const int*)d_in[2];
    const float* W1  = (const float*)d_in[3];
    const float* b1  = (const float*)d_in[4];
    const float* W2  = (const float*)d_in[5];
    const float* b2  = (const float*)d_in[6];
    const float* Wih = (const float*)d_in[7];
    const float* Whh = (const float*)d_in[8];
    const float* bih = (const float*)d_in[9];
    const float* bhh = (const float*)d_in[10];
    const float* Wc1 = (const float*)d_in[11];
    const float* bc1 = (const float*)d_in[12];
    const float* Wc2 = (const float*)d_in[13];
    const float* bc2 = (const float*)d_in[14];
    float* out = (float*)d_out;

    const int AGG_SMEM = (BM * ASTRIDE + KU_ * H_ + 2 * H_) * (int)sizeof(float);
    cudaFuncSetAttribute(k_aggemm, cudaFuncAttributeMaxDynamicSharedMemorySize, AGG_SMEM);

    const dim3 GRST((N_ / 4 + 255) / 256, T_);
    const dim3 GE4((E_ / 4 + 255) / 256, T_);
    const dim3 GFS(FB_ + SB_, T_);
    const dim3 GM((N_ + BM - 1) / BM, T_);
    const dim3 GR((N_ + 7) / 8, T_);

    k_reset<<<GRST, 256>>>(tgt);              // reset + seed fused
    k_prop<<<GE4, 256>>>(ei, 1);
    k_prop<<<GE4, 256>>>(ei, 2);
    k_count<<<GE4, 256>>>(ei);
    k_scan<<<T_, 1024>>>();
    k_fillscale<<<GFS, 256>>>(ei, x);         // CSR fill + dxl scale fused
    k_aggemm<<<GM, 256, AGG_SMEM>>>(W1, b1, W2);  // gather + GEMM + g_col fused
    k_col_argmax<<<GR, 256>>>(b2);
    k_top<<<T_, 128>>>(W1, b1, W2, b2);
    k_final<<<1, 128>>>(Wih, Whh, bih, bhh, Wc1, bc1, Wc2, bc2, out);
}

// round 7
// speedup vs baseline: 1.1066x; 1.1066x over previous
#include <cuda_runtime.h>
#include <math.h>

#define T_ 6
#define N_ 20000
#define E_ 400000
#define F_ 64
#define C_ 64
#define H_ 128
#define BIG_ 0x3fffffff

// ---------------- scratch (device globals; no allocation) ----------------
__device__ __align__(128) int   g_lvl[T_][N_];
__device__ __align__(128) int   g_count[T_][N_];
__device__ __align__(128) int   g_rowptr[T_][N_ + 1];
__device__ __align__(128) int   g_cursor[T_][N_];
__device__ __align__(128) int   g_csrsrc[T_][E_];
__device__ __align__(128) float g_dinv[T_][N_];
__device__ __align__(128) float g_buf1[T_][N_ * H_];   // g1 = dinv*(xl@W1)
__device__ __align__(128) float g_buf2[T_][N_ * H_];   // h1
__device__ __align__(128) float g_col[T_][N_];         // dinv*(h1 . W2[:,127])
__device__ unsigned long long   g_argmax[T_];
__device__ __align__(128) float g_seq[T_ * H_];

// ---------------- BFS branch: reset+seed fused, then 2 prop passes ----------------
__global__ void k_reset(const int* __restrict__ tgt) {
    int t = blockIdx.y;
    __shared__ int stgt[C_];
    if (threadIdx.x < C_) stgt[threadIdx.x] = tgt[t * C_ + threadIdx.x];
    __syncthreads();
    int i4 = (blockIdx.x * 256 + threadIdx.x) * 4;
    if (i4 < N_) {
        int4 v = make_int4(BIG_, BIG_, BIG_, BIG_);
#pragma unroll
        for (int j = 0; j < C_; j++) {
            int tg = stgt[j];
            if (tg == i4) v.x = 0;
            if (tg == i4 + 1) v.y = 0;
            if (tg == i4 + 2) v.z = 0;
            if (tg == i4 + 3) v.w = 0;
        }
        *(int4*)&g_lvl[t][i4] = v;
    }
    if (blockIdx.x == 0 && threadIdx.x == 0) g_argmax[t] = 0ULL;
}

// Level-stamped BFS iteration k: node is "in" at start of iter k iff lvl < k.
// Writes during iter k are exactly k, so stale reads cannot over-propagate.
__global__ void k_prop(const int* __restrict__ ei, int k) {
    int t = blockIdx.y;
    int i = blockIdx.x * blockDim.x + threadIdx.x;
    if (i >= E_) return;
    const int* src = ei + (size_t)t * 2 * E_;
    const int* dst = src + E_;
    int s = src[i], d = dst[i];
    int ls = g_lvl[t][s], ld = g_lvl[t][d];
    if (ls < k && ld > k) atomicMin(&g_lvl[t][d], k);
    if (ld < k && ls > k) atomicMin(&g_lvl[t][s], k);
}

// ---------------- CSR branch (FULL graph; independent of BFS) ----------------
__global__ void k_count(const int* __restrict__ ei) {
    int t = blockIdx.y;
    int i = blockIdx.x * blockDim.x + threadIdx.x;
    if (i >= E_) return;
    const int* dst = ei + (size_t)t * 2 * E_ + E_;
    atomicAdd(&g_count[t][dst[i]], 1);
}

__global__ void k_count_reset() {
    int t = blockIdx.y;
    int i = blockIdx.x * blockDim.x + threadIdx.x;
    if (i < N_) g_count[t][i] = 0;
}

__global__ void k_scan() {
    int t = blockIdx.x;
    const int CH = 20;
    __shared__ int s[1024];
    int tid = threadIdx.x;
    int base = tid * CH;
    int loc[CH];
    int sum = 0;
#pragma unroll
    for (int i = 0; i < CH; i++) {
        int idx = base + i;
        int c = (idx < N_) ? g_count[t][idx] : 0;
        loc[i] = sum;
        sum += c;
    }
    s[tid] = sum;
    __syncthreads();
    for (int off = 1; off < 1024; off <<= 1) {
        int v = (tid >= off) ? s[tid - off] : 0;
        __syncthreads();
        s[tid] += v;
        __syncthreads();
    }
    int excl = s[tid] - sum;
#pragma unroll
    for (int i = 0; i < CH; i++) {
        int idx = base + i;
        if (idx < N_) {
            int o = excl + loc[i];
            g_rowptr[t][idx] = o;
            g_cursor[t][idx] = o;
        }
    }
    if (tid == 1023) g_rowptr[t][N_] = s[1023];
}

__global__ void k_fill(const int* __restrict__ ei) {
    int t = blockIdx.y;
    int i = blockIdx.x * blockDim.x + threadIdx.x;
    if (i >= E_) return;
    const int* src = ei + (size_t)t * 2 * E_;
    const int* dst = src + E_;
    int s = src[i], d = dst[i];
    int p = atomicAdd(&g_cursor[t][d], 1);
    g_csrsrc[t][p] = s;
}

// ---------------- join: subgraph degree + dinv via CSR gather ----------------
__global__ void __launch_bounds__(256) k_deg() {
    int t = blockIdx.y;
    int tid = threadIdx.x;
    int warp = tid >> 5, lane = tid & 31;
    int row = blockIdx.x * 8 + warp;
    if (row >= N_) return;
    const int* __restrict__ lvl = g_lvl[t];
    bool in = lvl[row] < BIG_;
    int cnt = 0;
    if (in) {
        int s0 = g_rowptr[t][row], s1 = g_rowptr[t][row + 1];
        const int* __restrict__ csr = g_csrsrc[t];
        for (int j = s0 + lane; j < s1; j += 32) cnt += (lvl[csr[j]] < BIG_) ? 1 : 0;
    }
    cnt += __shfl_down_sync(0xffffffffu, cnt, 16);
    cnt += __shfl_down_sync(0xffffffffu, cnt, 8);
    cnt += __shfl_down_sync(0xffffffffu, cnt, 4);
    cnt += __shfl_down_sync(0xffffffffu, cnt, 2);
    cnt += __shfl_down_sync(0xffffffffu, cnt, 1);
    if (lane == 0) g_dinv[t][row] = in ? rsqrtf((float)cnt + 1.0f) : 0.0f;
}

// ---------------- GEMM1: g1[n,:] = dinv[n] * ([x[n],labels] @ W1) ----------------
#define BM 64
#define KC 32
__global__ void __launch_bounds__(256) k_gemm(const float* __restrict__ Abase, int K,
                                              const float* __restrict__ W, int addLabels,
                                              float* __restrict__ outBase) {
    int t = blockIdx.y;
    const float* A = Abase + (size_t)t * N_ * K;
    float* out = outBase + (size_t)t * N_ * H_;

    __shared__ float As[KC][BM + 4];
    __shared__ float Bs[KC][H_];
    int tid = threadIdx.x;
    int tc = tid & 31;
    int tr = tid >> 5;
    int m0 = blockIdx.x * BM;

    float acc[8][4];
#pragma unroll
    for (int i = 0; i < 8; i++)
#pragma unroll
        for (int j = 0; j < 4; j++) acc[i][j] = 0.0f;

    for (int kb = 0; kb < K; kb += KC) {
#pragma unroll
        for (int i = 0; i < 2; i++) {
            int e = tid + i * 256;
            int r = e >> 3;
            int kq = (e & 7) * 4;
            int gr = m0 + r;
            float4 v = make_float4(0.f, 0.f, 0.f, 0.f);
            if (gr < N_) v = *(const float4*)&A[(size_t)gr * K + kb + kq];
            As[kq + 0][r] = v.x;
            As[kq + 1][r] = v.y;
            As[kq + 2][r] = v.z;
            As[kq + 3][r] = v.w;
        }
#pragma unroll
        for (int i = 0; i < 4; i++) {
            int e = tid + i * 256;
            int kr = e >> 5;
            int cq = (e & 31) * 4;
            *(float4*)&Bs[kr][cq] = *(const float4*)&W[(size_t)(kb + kr) * H_ + cq];
        }
        __syncthreads();
#pragma unroll
        for (int k = 0; k < KC; k++) {
            float4 b = *(float4*)&Bs[k][tc * 4];
            float4 al = *(float4*)&As[k][tr * 8];
            float4 ah = *(float4*)&As[k][tr * 8 + 4];
            float a[8] = {al.x, al.y, al.z, al.w, ah.x, ah.y, ah.z, ah.w};
#pragma unroll
            for (int i = 0; i < 8; i++) {
                acc[i][0] = fmaf(a[i], b.x, acc[i][0]);
                acc[i][1] = fmaf(a[i], b.y, acc[i][1]);
                acc[i][2] = fmaf(a[i], b.z, acc[i][2]);
                acc[i][3] = fmaf(a[i], b.w, acc[i][3]);
            }
        }
        __syncthreads();
    }

    float4 w64 = make_float4(0.f, 0.f, 0.f, 0.f);
    float4 w65 = make_float4(0.f, 0.f, 0.f, 0.f);
    if (addLabels) {
        w64 = *(const float4*)&W[(size_t)64 * H_ + tc * 4];
        w65 = *(const float4*)&W[(size_t)65 * H_ + tc * 4];
    }
#pragma unroll
    for (int i = 0; i < 8; i++) {
        int r = m0 + tr * 8 + i;
        if (r >= N_) break;
        float e0 = acc[i][0], e1 = acc[i][1], e2 = acc[i][2], e3 = acc[i][3];
        if (addLabels) {
            int lv = g_lvl[t][r];
            float l0 = (lv == 0) ? 1.0f : 0.0f;
            float l1 = (lv > 0 && lv < BIG_) ? 1.0f : 0.0f;
            e0 += l0 * w64.x + l1 * w65.x;
            e1 += l0 * w64.y + l1 * w65.y;
            e2 += l0 * w64.z + l1 * w65.z;
            e3 += l0 * w64.w + l1 * w65.w;
        }
        float d = g_dinv[t][r];
        float4 o = make_float4(e0 * d, e1 * d, e2 * d, e3 * d);
        *(float4*)&out[(size_t)r * H_ + tc * 4] = o;
    }
}

__device__ __forceinline__ float warp_sum(float v) {
    v += __shfl_down_sync(0xffffffffu, v, 16);
    v += __shfl_down_sync(0xffffffffu, v, 8);
    v += __shfl_down_sync(0xffffffffu, v, 4);
    v += __shfl_down_sync(0xffffffffu, v, 2);
    v += __shfl_down_sync(0xffffffffu, v, 1);
    return v;
}

// ---------------- SpMM1 (warp-per-row, float4, FULL CSR) + fused g2col ----------------
// non-subgraph sources have g1 = 0 (dinv factor), so full-CSR sums are exact.
__global__ void __launch_bounds__(256) k_spmm1(const float* __restrict__ gbase,
                                               const float* __restrict__ b1,
                                               const float* __restrict__ W2,
                                               float* __restrict__ h1base) {
    int t = blockIdx.y;
    const float* g = gbase + (size_t)t * N_ * H_;
    float* h1 = h1base + (size_t)t * N_ * H_;

    __shared__ float w2c[H_];
    int tid = threadIdx.x;
    if (tid < H_) w2c[tid] = W2[(size_t)tid * H_ + (H_ - 1)];
    __syncthreads();

    int warp = tid >> 5, lane = tid & 31;
    int row = blockIdx.x * 8 + warp;
    if (row >= N_) return;

    int s0 = g_rowptr[t][row], s1 = g_rowptr[t][row + 1];
    const int* __restrict__ csr = g_csrsrc[t];
    int co = lane * 4;

    float4 a0 = make_float4(0.f, 0.f, 0.f, 0.f);
    float4 a1 = make_float4(0.f, 0.f, 0.f, 0.f);
    float4 a2 = make_float4(0.f, 0.f, 0.f, 0.f);
    float4 a3 = make_float4(0.f, 0.f, 0.f, 0.f);
    int j = s0;
    for (; j + 4 <= s1; j += 4) {
        int i0 = csr[j], i1 = csr[j + 1], i2 = csr[j + 2], i3 = csr[j + 3];
        float4 v0 = *(const float4*)&g[(size_t)i0 * H_ + co];
        float4 v1 = *(const float4*)&g[(size_t)i1 * H_ + co];
        float4 v2 = *(const float4*)&g[(size_t)i2 * H_ + co];
        float4 v3 = *(const float4*)&g[(size_t)i3 * H_ + co];
        a0.x += v0.x; a0.y += v0.y; a0.z += v0.z; a0.w += v0.w;
        a1.x += v1.x; a1.y += v1.y; a1.z += v1.z; a1.w += v1.w;
        a2.x += v2.x; a2.y += v2.y; a2.z += v2.z; a2.w += v2.w;
        a3.x += v3.x; a3.y += v3.y; a3.z += v3.z; a3.w += v3.w;
    }
    for (; j < s1; j++) {
        float4 v = *(const float4*)&g[(size_t)csr[j] * H_ + co];
        a0.x += v.x; a0.y += v.y; a0.z += v.z; a0.w += v.w;
    }
    float4 self = *(const float4*)&g[(size_t)row * H_ + co];
    float ax = (a0.x + a1.x) + (a2.x + a3.x) + self.x;
    float ay = (a0.y + a1.y) + (a2.y + a3.y) + self.y;
    float az = (a0.z + a1.z) + (a2.z + a3.z) + self.z;
    float aw = (a0.w + a1.w) + (a2.w + a3.w) + self.w;

    float d = g_dinv[t][row];
    float4 bb = *(const float4*)&b1[co];
    float4 v;
    v.x = fmaxf(fmaf(d, ax, bb.x), 0.f);
    v.y = fmaxf(fmaf(d, ay, bb.y), 0.f);
    v.z = fmaxf(fmaf(d, az, bb.z), 0.f);
    v.w = fmaxf(fmaf(d, aw, bb.w), 0.f);
    *(float4*)&h1[(size_t)row * H_ + co] = v;

    float dot = v.x * w2c[co] + v.y * w2c[co + 1] + v.z * w2c[co + 2] + v.w * w2c[co + 3];
    dot = warp_sum(dot);
    if (lane == 0) g_col[t][row] = d * dot;
}

// ---------------- layer-2 scalar aggregation + fused argmax ----------------
__global__ void __launch_bounds__(256) k_col_argmax(const float* __restrict__ b2) {
    int t = blockIdx.y;
    int tid = threadIdx.x;
    int warp = tid >> 5, lane = tid & 31;
    int row = blockIdx.x * 8 + warp;
    unsigned long long p = 0ULL;
    float b = b2[H_ - 1];
    if (row < N_) {
        int s0 = g_rowptr[t][row], s1 = g_rowptr[t][row + 1];
        const int* __restrict__ csr = g_csrsrc[t];
        const float* __restrict__ col = g_col[t];
        float s = 0.f;
        for (int j = s0 + lane; j < s1; j += 32) s += col[csr[j]];
        s = warp_sum(s);
        if (lane == 0) {
            float d = g_dinv[t][row];
            if (d > 0.f) {
                float v = fmaxf(fmaf(d, s + col[row], b), 0.f);
                p = ((unsigned long long)__float_as_uint(v) << 32) |
                    (unsigned int)(0x7fffffff - row);
            }
        }
    }
    __shared__ unsigned long long sm[8];
    if (lane == 0) sm[warp] = p;
    __syncthreads();
    if (tid == 0) {
        unsigned long long m = sm[0];
#pragma unroll
        for (int i = 1; i < 8; i++) m = (sm[i] > m) ? sm[i] : m;
        if (m) atomicMax(&g_argmax[t], m);
    }
}

// ---------------- reconstruct h2[top,:] -> g_seq (dinv weights kill non-sub) ----------
__global__ void __launch_bounds__(128) k_top(const float* __restrict__ h1base,
                                             const float* __restrict__ W2,
                                             const float* __restrict__ b2) {
    int t = blockIdx.x;
    const float* h1 = h1base + (size_t)t * N_ * H_;
    int top = 0x7fffffff - (int)(g_argmax[t] & 0x7fffffffULL);
    int c = threadIdx.x;
    __shared__ float svec[H_];

    int s0 = g_rowptr[t][top], s1 = g_rowptr[t][top + 1];
    float dtop = g_dinv[t][top];
    float acc = dtop * h1[(size_t)top * H_ + c];
    for (int j = s0; j < s1; j++) {
        int s = g_csrsrc[t][j];
        acc += g_dinv[t][s] * h1[(size_t)s * H_ + c];
    }
    svec[c] = acc;
    __syncthreads();

    float o = 0.f;
#pragma unroll 4
    for (int k = 0; k < H_; k++) o = fmaf(svec[k], W2[(size_t)k * H_ + c], o);
    g_seq[t * H_ + c] = fmaxf(fmaf(dtop, o, b2[c]), 0.f);
}

// ---------------- GRU + MLP head ----------------
__global__ void __launch_bounds__(128) k_final(const float* __restrict__ Wih,
                                               const float* __restrict__ Whh,
                                               const float* __restrict__ bih,
                                               const float* __restrict__ bhh,
                                               const float* __restrict__ Wc1,
                                               const float* __restrict__ bc1,
                                               const float* __restrict__ Wc2,
                                               const float* __restrict__ bc2,
                                               float* __restrict__ out) {
    __shared__ float h[H_], xt[H_], sgi[3 * H_], sgh[3 * H_], hid[H_ / 2];
    int tid = threadIdx.x, lane = tid & 31, w = tid >> 5;
    h[tid] = 0.0f;
    __syncthreads();
    for (int t = 0; t < T_; t++) {
        xt[tid] = g_seq[t * H_ + tid];
        __syncthreads();
        for (int o = w; o < 3 * H_; o += 4) {
            float si = 0.f, sh = 0.f;
            for (int k = lane; k < H_; k += 32) {
                si += xt[k] * Wih[(size_t)o * H_ + k];
                sh += h[k] * Whh[(size_t)o * H_ + k];
            }
            si = warp_sum(si);
            sh = warp_sum(sh);
            if (lane == 0) {
                sgi[o] = si + bih[o];
                sgh[o] = sh + bhh[o];
            }
        }
        __syncthreads();
        float r = 1.0f / (1.0f + expf(-(sgi[tid] + sgh[tid])));
        float z = 1.0f / (1.0f + expf(-(sgi[tid + H_] + sgh[tid + H_])));
        float n = tanhf(sgi[tid + 2 * H_] + r * sgh[tid + 2 * H_]);
        float hn = (1.0f - z) * n + z * h[tid];
        __syncthreads();
        h[tid] = hn;
        __syncthreads();
    }
    if (tid < H_ / 2) {
        float s = bc1[tid];
        for (int k = 0; k < H_; k++) s += h[k] * Wc1[(size_t)k * (H_ / 2) + tid];
        hid[tid] = fmaxf(s, 0.0f);
    }
    __syncthreads();
    if (tid == 0) {
        float s = bc2[0];
        for (int j = 0; j < H_ / 2; j++) s += hid[j] * Wc2[j];
        out[0] = 1.0f / (1.0f + expf(-s));
    }
}

// ---------------- launch (fork-join: CSR branch || BFS branch) ----------------
extern "C" void kernel_launch(void* const* d_in, const int* in_sizes, int n_in,
                              void* d_out, int out_size) {
    const float* x   = (const float*)d_in[0];
    const int*   ei  = (const int*)d_in[1];
    const int*   tgt = (const int*)d_in[2];
    const float* W1  = (const float*)d_in[3];
    const float* b1  = (const float*)d_in[4];
    const float* W2  = (const float*)d_in[5];
    const float* b2  = (const float*)d_in[6];
    const float* Wih = (const float*)d_in[7];
    const float* Whh = (const float*)d_in[8];
    const float* bih = (const float*)d_in[9];
    const float* bhh = (const float*)d_in[10];
    const float* Wc1 = (const float*)d_in[11];
    const float* bc1 = (const float*)d_in[12];
    const float* Wc2 = (const float*)d_in[13];
    const float* bc2 = (const float*)d_in[14];
    float* out = (float*)d_out;

    float *buf1 = nullptr, *buf2 = nullptr;
    cudaGetSymbolAddress((void**)&buf1, g_buf1);
    cudaGetSymbolAddress((void**)&buf2, g_buf2);

    const dim3 GRST((N_ / 4 + 255) / 256, T_);
    const dim3 GN((N_ + 255) / 256, T_);
    const dim3 GE((E_ + 255) / 256, T_);
    const dim3 GM((N_ + BM - 1) / BM, T_);
    const dim3 GR((N_ + 7) / 8, T_);

    cudaStream_t s2;
    cudaStreamCreateWithFlags(&s2, cudaStreamNonBlocking);
    cudaEvent_t evF, evJ;
    cudaEventCreateWithFlags(&evF, cudaEventDisableTiming);
    cudaEventCreateWithFlags(&evJ, cudaEventDisableTiming);

    // fork: side stream builds full-graph CSR (no BFS dependence)
    cudaEventRecord(evF, cudaStreamPerThread);
    cudaStreamWaitEvent(s2, evF, 0);
    k_count_reset<<<GN, 256, 0, s2>>>();
    k_count<<<GE, 256, 0, s2>>>(ei);
    k_scan<<<T_, 1024, 0, s2>>>();
    k_fill<<<GE, 256, 0, s2>>>(ei);
    cudaEventRecord(evJ, s2);

    // main stream: BFS
    k_reset<<<GRST, 256>>>(tgt);
    k_prop<<<GE, 256>>>(ei, 1);
    k_prop<<<GE, 256>>>(ei, 2);

    // join, then the rest of the pipeline
    cudaStreamWaitEvent(cudaStreamPerThread, evJ, 0);
    k_deg<<<GR, 256>>>();
    k_gemm<<<GM, 256>>>(x, F_, W1, 1, buf1);
    k_spmm1<<<GR, 256>>>(buf1, b1, W2, buf2);
    k_col_argmax<<<GR, 256>>>(b2);
    k_top<<<T_, 128>>>(buf2, W2, b2);
    k_final<<<1, 128>>>(Wih, Whh, bih, bhh, Wc1, bc1, Wc2, bc2, out);

    // cleanup (deferred-safe; skip stream destroy mid-capture)
    cudaStreamCaptureStatus cs = cudaStreamCaptureStatusNone;
    cudaStreamIsCapturing(cudaStreamPerThread, &cs);
    cudaEventDestroy(evF);
    cudaEventDestroy(evJ);
    if (cs == cudaStreamCaptureStatusNone) cudaStreamDestroy(s2);
}

// round 8
// speedup vs baseline: 1.1124x; 1.0053x over previous
#include <cuda_runtime.h>
#include <cuda_fp16.h>
#include <math.h>

#define T_ 6
#define N_ 20000
#define E_ 400000
#define F_ 64
#define C_ 64
#define H_ 128
#define BIG_ 0x3fffffff

// ---------------- scratch (device globals; no allocation) ----------------
__device__ __align__(128) int    g_lvl[T_][N_];
__device__ __align__(128) int    g_count[T_][N_];
__device__ __align__(128) int    g_rowptr[T_][N_ + 1];
__device__ __align__(128) int    g_cursor[T_][N_];
__device__ __align__(128) int    g_csrsrc[T_][E_];
__device__ __align__(128) float  g_dinv[T_][N_];
__device__ __align__(128) __half g_g1[T_][N_ * H_];   // g1 = dinv*(xl@W1), fp16
__device__ __align__(128) float  g_col[T_][N_];       // dinv*(h1 . W2[:,127])
__device__ unsigned long long    g_argmax[T_];
__device__ __align__(128) float  g_seq[T_ * H_];

// ---------------- BFS branch ----------------
__global__ void k_reset(const int* __restrict__ tgt) {
    int t = blockIdx.y;
    __shared__ int stgt[C_];
    if (threadIdx.x < C_) stgt[threadIdx.x] = tgt[t * C_ + threadIdx.x];
    __syncthreads();
    int i4 = (blockIdx.x * 256 + threadIdx.x) * 4;
    if (i4 < N_) {
        int4 v = make_int4(BIG_, BIG_, BIG_, BIG_);
#pragma unroll
        for (int j = 0; j < C_; j++) {
            int tg = stgt[j];
            if (tg == i4) v.x = 0;
            if (tg == i4 + 1) v.y = 0;
            if (tg == i4 + 2) v.z = 0;
            if (tg == i4 + 3) v.w = 0;
        }
        *(int4*)&g_lvl[t][i4] = v;
    }
    if (blockIdx.x == 0 && threadIdx.x == 0) g_argmax[t] = 0ULL;
}

// Level-stamped BFS (writes during iter k are exactly k; lvl<k predicate safe).
__global__ void k_prop(const int* __restrict__ ei, int k) {
    int t = blockIdx.y;
    int i = blockIdx.x * blockDim.x + threadIdx.x;
    if (i >= E_) return;
    const int* src = ei + (size_t)t * 2 * E_;
    const int* dst = src + E_;
    int s = src[i], d = dst[i];
    int ls = g_lvl[t][s], ld = g_lvl[t][d];
    if (ls < k && ld > k) atomicMin(&g_lvl[t][d], k);
    if (ld < k && ls > k) atomicMin(&g_lvl[t][s], k);
}

// ---------------- CSR branch (FULL graph; independent of BFS) ----------------
__global__ void k_count_reset() {
    int t = blockIdx.y;
    int i = blockIdx.x * blockDim.x + threadIdx.x;
    if (i < N_) g_count[t][i] = 0;
}

__global__ void k_count(const int* __restrict__ ei) {
    int t = blockIdx.y;
    int i = blockIdx.x * blockDim.x + threadIdx.x;
    if (i >= E_) return;
    const int* dst = ei + (size_t)t * 2 * E_ + E_;
    atomicAdd(&g_count[t][dst[i]], 1);
}

__global__ void k_scan() {
    int t = blockIdx.x;
    const int CH = 20;
    __shared__ int s[1024];
    int tid = threadIdx.x;
    int base = tid * CH;
    int loc[CH];
    int sum = 0;
#pragma unroll
    for (int i = 0; i < CH; i++) {
        int idx = base + i;
        int c = (idx < N_) ? g_count[t][idx] : 0;
        loc[i] = sum;
        sum += c;
    }
    s[tid] = sum;
    __syncthreads();
    for (int off = 1; off < 1024; off <<= 1) {
        int v = (tid >= off) ? s[tid - off] : 0;
        __syncthreads();
        s[tid] += v;
        __syncthreads();
    }
    int excl = s[tid] - sum;
#pragma unroll
    for (int i = 0; i < CH; i++) {
        int idx = base + i;
        if (idx < N_) {
            int o = excl + loc[i];
            g_rowptr[t][idx] = o;
            g_cursor[t][idx] = o;
        }
    }
    if (tid == 1023) g_rowptr[t][N_] = s[1023];
}

__global__ void k_fill(const int* __restrict__ ei) {
    int t = blockIdx.y;
    int i = blockIdx.x * blockDim.x + threadIdx.x;
    if (i >= E_) return;
    const int* src = ei + (size_t)t * 2 * E_;
    const int* dst = src + E_;
    int s = src[i], d = dst[i];
    int p = atomicAdd(&g_cursor[t][d], 1);
    g_csrsrc[t][p] = s;
}

// ---------------- join: subgraph degree + dinv ----------------
__global__ void __launch_bounds__(256) k_deg() {
    int t = blockIdx.y;
    int tid = threadIdx.x;
    int warp = tid >> 5, lane = tid & 31;
    int row = blockIdx.x * 8 + warp;
    if (row >= N_) return;
    const int* __restrict__ lvl = g_lvl[t];
    bool in = lvl[row] < BIG_;
    int cnt = 0;
    if (in) {
        int s0 = g_rowptr[t][row], s1 = g_rowptr[t][row + 1];
        const int* __restrict__ csr = g_csrsrc[t];
        for (int j = s0 + lane; j < s1; j += 32) cnt += (lvl[csr[j]] < BIG_) ? 1 : 0;
    }
    cnt += __shfl_down_sync(0xffffffffu, cnt, 16);
    cnt += __shfl_down_sync(0xffffffffu, cnt, 8);
    cnt += __shfl_down_sync(0xffffffffu, cnt, 4);
    cnt += __shfl_down_sync(0xffffffffu, cnt, 2);
    cnt += __shfl_down_sync(0xffffffffu, cnt, 1);
    if (lane == 0) g_dinv[t][row] = in ? rsqrtf((float)cnt + 1.0f) : 0.0f;
}

// ---------------- GEMM1: g1(half)[n,:] = dinv[n]*([x[n],labels]@W1) ----------------
// 128x128 block tile, 256 threads as 16x16, 8x8 micro-tile, K-chunks of 32.
#define BM2 128
#define KC 32
__global__ void __launch_bounds__(256) k_gemm(const float* __restrict__ x,
                                              const float* __restrict__ W1) {
    int t = blockIdx.y;
    const float* A = x + (size_t)t * N_ * F_;
    __half* out = g_g1[t];

    __shared__ float As[KC][BM2 + 4];
    __shared__ float Bs[KC][H_];
    int tid = threadIdx.x;
    int tx = tid & 15;   // col group: cols tx*8..+7
    int ty = tid >> 4;   // row group: rows ty*8..+7
    int m0 = blockIdx.x * BM2;

    float acc[8][8];
#pragma unroll
    for (int i = 0; i < 8; i++)
#pragma unroll
        for (int j = 0; j < 8; j++) acc[i][j] = 0.0f;

    for (int kb = 0; kb < F_; kb += KC) {
        // A tile: 128 rows x 32 k = 1024 quads
#pragma unroll
        for (int i = 0; i < 4; i++) {
            int e = tid + i * 256;
            int r = e >> 3;
            int kq = (e & 7) * 4;
            int gr = m0 + r;
            float4 v = make_float4(0.f, 0.f, 0.f, 0.f);
            if (gr < N_) v = *(const float4*)&A[(size_t)gr * F_ + kb + kq];
            As[kq + 0][r] = v.x;
            As[kq + 1][r] = v.y;
            As[kq + 2][r] = v.z;
            As[kq + 3][r] = v.w;
        }
        // W tile: 32 x 128 = 1024 quads
#pragma unroll
        for (int i = 0; i < 4; i++) {
            int e = tid + i * 256;
            int kr = e >> 5;
            int cq = (e & 31) * 4;
            *(float4*)&Bs[kr][cq] = *(const float4*)&W1[(size_t)(kb + kr) * H_ + cq];
        }
        __syncthreads();
#pragma unroll
        for (int k = 0; k < KC; k++) {
            float4 b0 = *(float4*)&Bs[k][tx * 8];
            float4 b1v = *(float4*)&Bs[k][tx * 8 + 4];
            float4 a0 = *(float4*)&As[k][ty * 8];
            float4 a1 = *(float4*)&As[k][ty * 8 + 4];
            float av[8] = {a0.x, a0.y, a0.z, a0.w, a1.x, a1.y, a1.z, a1.w};
            float bv[8] = {b0.x, b0.y, b0.z, b0.w, b1v.x, b1v.y, b1v.z, b1v.w};
#pragma unroll
            for (int i = 0; i < 8; i++)
#pragma unroll
                for (int j = 0; j < 8; j++) acc[i][j] = fmaf(av[i], bv[j], acc[i][j]);
        }
        __syncthreads();
    }

    // label rows 64 (center) / 65 (other-sub)
    float w64[8], w65[8];
#pragma unroll
    for (int j = 0; j < 8; j++) {
        w64[j] = W1[(size_t)64 * H_ + tx * 8 + j];
        w65[j] = W1[(size_t)65 * H_ + tx * 8 + j];
    }
#pragma unroll
    for (int i = 0; i < 8; i++) {
        int r = m0 + ty * 8 + i;
        if (r >= N_) break;
        int lv = g_lvl[t][r];
        float l0 = (lv == 0) ? 1.0f : 0.0f;
        float l1 = (lv > 0 && lv < BIG_) ? 1.0f : 0.0f;
        float d = g_dinv[t][r];
        __half2 p[4];
#pragma unroll
        for (int j = 0; j < 4; j++) {
            float e0 = d * (acc[i][2 * j] + l0 * w64[2 * j] + l1 * w65[2 * j]);
            float e1 = d * (acc[i][2 * j + 1] + l0 * w64[2 * j + 1] + l1 * w65[2 * j + 1]);
            p[j] = __floats2half2_rn(e0, e1);
        }
        uint4 o = make_uint4(*(unsigned*)&p[0], *(unsigned*)&p[1],
                             *(unsigned*)&p[2], *(unsigned*)&p[3]);
        *(uint4*)&out[(size_t)r * H_ + tx * 8] = o;
    }
}

__device__ __forceinline__ float warp_sum(float v) {
    v += __shfl_down_sync(0xffffffffu, v, 16);
    v += __shfl_down_sync(0xffffffffu, v, 8);
    v += __shfl_down_sync(0xffffffffu, v, 4);
    v += __shfl_down_sync(0xffffffffu, v, 2);
    v += __shfl_down_sync(0xffffffffu, v, 1);
    return v;
}

// ---------------- SpMM1 over half g1 -> g_col only (no h1 write) ----------------
// h1[n,c] = relu(dinv[n]*(sum g1[src,c] + g1[n,c]) + b1[c]) (kept in regs)
// g_col[n] = dinv[n] * sum_c h1[n,c]*W2[c,127]
__global__ void __launch_bounds__(256) k_spmm1(const float* __restrict__ b1,
                                               const float* __restrict__ W2) {
    int t = blockIdx.y;
    const __half* __restrict__ g = g_g1[t];

    __shared__ float w2c[H_];
    int tid = threadIdx.x;
    if (tid < H_) w2c[tid] = W2[(size_t)tid * H_ + (H_ - 1)];
    __syncthreads();

    int warp = tid >> 5, lane = tid & 31;
    int row = blockIdx.x * 8 + warp;
    if (row >= N_) return;

    int s0 = g_rowptr[t][row], s1 = g_rowptr[t][row + 1];
    const int* __restrict__ csr = g_csrsrc[t];
    int co = lane * 4;  // 4 channels per lane = 8 bytes (uint2)

    float ax = 0.f, ay = 0.f, az = 0.f, aw = 0.f;
    int j = s0;
    for (; j + 4 <= s1; j += 4) {
        int i0 = csr[j], i1 = csr[j + 1], i2 = csr[j + 2], i3 = csr[j + 3];
        uint2 r0 = *(const uint2*)&g[(size_t)i0 * H_ + co];
        uint2 r1 = *(const uint2*)&g[(size_t)i1 * H_ + co];
        uint2 r2 = *(const uint2*)&g[(size_t)i2 * H_ + co];
        uint2 r3 = *(const uint2*)&g[(size_t)i3 * H_ + co];
        float2 f;
        f = __half22float2(*(__half2*)&r0.x); ax += f.x; ay += f.y;
        f = __half22float2(*(__half2*)&r0.y); az += f.x; aw += f.y;
        f = __half22float2(*(__half2*)&r1.x); ax += f.x; ay += f.y;
        f = __half22float2(*(__half2*)&r1.y); az += f.x; aw += f.y;
        f = __half22float2(*(__half2*)&r2.x); ax += f.x; ay += f.y;
        f = __half22float2(*(__half2*)&r2.y); az += f.x; aw += f.y;
        f = __half22float2(*(__half2*)&r3.x); ax += f.x; ay += f.y;
        f = __half22float2(*(__half2*)&r3.y); az += f.x; aw += f.y;
    }
    for (; j < s1; j++) {
        uint2 r0 = *(const uint2*)&g[(size_t)csr[j] * H_ + co];
        float2 f;
        f = __half22float2(*(__half2*)&r0.x); ax += f.x; ay += f.y;
        f = __half22float2(*(__half2*)&r0.y); az += f.x; aw += f.y;
    }
    {   // self
        uint2 r0 = *(const uint2*)&g[(size_t)row * H_ + co];
        float2 f;
        f = __half22float2(*(__half2*)&r0.x); ax += f.x; ay += f.y;
        f = __half22float2(*(__half2*)&r0.y); az += f.x; aw += f.y;
    }

    float d = g_dinv[t][row];
    float4 bb = *(const float4*)&b1[co];
    float h0 = fmaxf(fmaf(d, ax, bb.x), 0.f);
    float h1 = fmaxf(fmaf(d, ay, bb.y), 0.f);
    float h2 = fmaxf(fmaf(d, az, bb.z), 0.f);
    float h3 = fmaxf(fmaf(d, aw, bb.w), 0.f);

    float dot = h0 * w2c[co] + h1 * w2c[co + 1] + h2 * w2c[co + 2] + h3 * w2c[co + 3];
    dot = warp_sum(dot);
    if (lane == 0) g_col[t][row] = d * dot;
}

// ---------------- layer-2 scalar aggregation + fused argmax ----------------
__global__ void __launch_bounds__(256) k_col_argmax(const float* __restrict__ b2) {
    int t = blockIdx.y;
    int tid = threadIdx.x;
    int warp = tid >> 5, lane = tid & 31;
    int row = blockIdx.x * 8 + warp;
    unsigned long long p = 0ULL;
    float b = b2[H_ - 1];
    if (row < N_) {
        int s0 = g_rowptr[t][row], s1 = g_rowptr[t][row + 1];
        const int* __restrict__ csr = g_csrsrc[t];
        const float* __restrict__ col = g_col[t];
        float s = 0.f;
        for (int j = s0 + lane; j < s1; j += 32) s += col[csr[j]];
        s = warp_sum(s);
        if (lane == 0) {
            float d = g_dinv[t][row];
            if (d > 0.f) {
                float v = fmaxf(fmaf(d, s + col[row], b), 0.f);
                p = ((unsigned long long)__float_as_uint(v) << 32) |
                    (unsigned int)(0x7fffffff - row);
            }
        }
    }
    __shared__ unsigned long long sm[8];
    if (lane == 0) sm[warp] = p;
    __syncthreads();
    if (tid == 0) {
        unsigned long long m = sm[0];
#pragma unroll
        for (int i = 1; i < 8; i++) m = (sm[i] > m) ? sm[i] : m;
        if (m) atomicMax(&g_argmax[t], m);
    }
}

// ---------------- recompute h1 on top's nbhd from half g1; h2[top,:] -> g_seq --------
__global__ void __launch_bounds__(128) k_top(const float* __restrict__ b1,
                                             const float* __restrict__ W2,
                                             const float* __restrict__ b2) {
    int t = blockIdx.x;
    int top = 0x7fffffff - (int)(g_argmax[t] & 0x7fffffffULL);
    int c = threadIdx.x;
    __shared__ float svec[H_];
    const __half* __restrict__ g = g_g1[t];
    const int* __restrict__ csr = g_csrsrc[t];

    int s0 = g_rowptr[t][top], s1 = g_rowptr[t][top + 1];
    float sv = 0.f;
    float bc = b1[c];
    for (int idx = -1; idx < s1 - s0; idx++) {
        int u = (idx < 0) ? top : csr[s0 + idx];
        float du = g_dinv[t][u];
        if (du > 0.f) {  // non-sub neighbors contribute 0 (dinv weight)
            int u0 = g_rowptr[t][u], u1 = g_rowptr[t][u + 1];
            float a0 = __half2float(g[(size_t)u * H_ + c]);
            float a1 = 0.f, a2 = 0.f, a3 = 0.f;
            int j = u0;
            for (; j + 4 <= u1; j += 4) {
                a0 += __half2float(g[(size_t)csr[j] * H_ + c]);
                a1 += __half2float(g[(size_t)csr[j + 1] * H_ + c]);
                a2 += __half2float(g[(size_t)csr[j + 2] * H_ + c]);
                a3 += __half2float(g[(size_t)csr[j + 3] * H_ + c]);
            }
            for (; j < u1; j++) a0 += __half2float(g[(size_t)csr[j] * H_ + c]);
            float agg = (a0 + a1) + (a2 + a3);
            float h = fmaxf(fmaf(du, agg, bc), 0.f);
            sv += du * h;
        }
    }
    svec[c] = sv;
    __syncthreads();

    float o = 0.f;
#pragma unroll 4
    for (int k = 0; k < H_; k++) o = fmaf(svec[k], W2[(size_t)k * H_ + c], o);
    float dtop = g_dinv[t][top];
    g_seq[t * H_ + c] = fmaxf(fmaf(dtop, o, b2[c]), 0.f);
}

// ---------------- GRU + MLP head ----------------
__global__ void __launch_bounds__(128) k_final(const float* __restrict__ Wih,
                                               const float* __restrict__ Whh,
                                               const float* __restrict__ bih,
                                               const float* __restrict__ bhh,
                                               const float* __restrict__ Wc1,
                                               const float* __restrict__ bc1,
                                               const float* __restrict__ Wc2,
                                               const float* __restrict__ bc2,
                                               float* __restrict__ out) {
    __shared__ float h[H_], xt[H_], sgi[3 * H_], sgh[3 * H_], hid[H_ / 2];
    int tid = threadIdx.x, lane = tid & 31, w = tid >> 5;
    h[tid] = 0.0f;
    __syncthreads();
    for (int t = 0; t < T_; t++) {
        xt[tid] = g_seq[t * H_ + tid];
        __syncthreads();
        for (int o = w; o < 3 * H_; o += 4) {
            float si = 0.f, sh = 0.f;
            for (int k = lane; k < H_; k += 32) {
                si += xt[k] * Wih[(size_t)o * H_ + k];
                sh += h[k] * Whh[(size_t)o * H_ + k];
            }
            si = warp_sum(si);
            sh = warp_sum(sh);
            if (lane == 0) {
                sgi[o] = si + bih[o];
                sgh[o] = sh + bhh[o];
            }
        }
        __syncthreads();
        float r = 1.0f / (1.0f + expf(-(sgi[tid] + sgh[tid])));
        float z = 1.0f / (1.0f + expf(-(sgi[tid + H_] + sgh[tid + H_])));
        float n = tanhf(sgi[tid + 2 * H_] + r * sgh[tid + 2 * H_]);
        float hn = (1.0f - z) * n + z * h[tid];
        __syncthreads();
        h[tid] = hn;
        __syncthreads();
    }
    if (tid < H_ / 2) {
        float s = bc1[tid];
        for (int k = 0; k < H_; k++) s += h[k] * Wc1[(size_t)k * (H_ / 2) + tid];
        hid[tid] = fmaxf(s, 0.0f);
    }
    __syncthreads();
    if (tid == 0) {
        float s = bc2[0];
        for (int j = 0; j < H_ / 2; j++) s += hid[j] * Wc2[j];
        out[0] = 1.0f / (1.0f + expf(-s));
    }
}

// ---------------- launch (fork-join: CSR branch || BFS branch) ----------------
extern "C" void kernel_launch(void* const* d_in, const int* in_sizes, int n_in,
                              void* d_out, int out_size) {
    const float* x   = (const float*)d_in[0];
    const int*   ei  = (const int*)d_in[1];
    const int*   tgt = (const int*)d_in[2];
    const float* W1  = (const float*)d_in[3];
    const float* b1  = (const float*)d_in[4];
    const float* W2  = (const float*)d_in[5];
    const float* b2  = (const float*)d_in[6];
    const float* Wih = (const float*)d_in[7];
    const float* Whh = (const float*)d_in[8];
    const float* bih = (const float*)d_in[9];
    const float* bhh = (const float*)d_in[10];
    const float* Wc1 = (const float*)d_in[11];
    const float* bc1 = (const float*)d_in[12];
    const float* Wc2 = (const float*)d_in[13];
    const float* bc2 = (const float*)d_in[14];
    float* out = (float*)d_out;

    const dim3 GRST((N_ / 4 + 255) / 256, T_);
    const dim3 GN((N_ + 255) / 256, T_);
    const dim3 GE((E_ + 255) / 256, T_);
    const dim3 GM((N_ + BM2 - 1) / BM2, T_);
    const dim3 GR((N_ + 7) / 8, T_);

    cudaStream_t s2;
    cudaStreamCreateWithFlags(&s2, cudaStreamNonBlocking);
    cudaEvent_t evF, evJ;
    cudaEventCreateWithFlags(&evF, cudaEventDisableTiming);
    cudaEventCreateWithFlags(&evJ, cudaEventDisableTiming);

    // fork: side stream builds full-graph CSR (no BFS dependence)
    cudaEventRecord(evF, cudaStreamPerThread);
    cudaStreamWaitEvent(s2, evF, 0);
    k_count_reset<<<GN, 256, 0, s2>>>();
    k_count<<<GE, 256, 0, s2>>>(ei);
    k_scan<<<T_, 1024, 0, s2>>>();
    k_fill<<<GE, 256, 0, s2>>>(ei);
    cudaEventRecord(evJ, s2);

    // main stream: BFS
    k_reset<<<GRST, 256>>>(tgt);
    k_prop<<<GE, 256>>>(ei, 1);
    k_prop<<<GE, 256>>>(ei, 2);

    // join, then the rest of the pipeline
    cudaStreamWaitEvent(cudaStreamPerThread, evJ, 0);
    k_deg<<<GR, 256>>>();
    k_gemm<<<GM, 256>>>(x, W1);          // g1 (half) = dinv*(xl@W1)
    k_spmm1<<<GR, 256>>>(b1, W2);        // -> g_col only
    k_col_argmax<<<GR, 256>>>(b2);
    k_top<<<T_, 128>>>(b1, W2, b2);
    k_final<<<1, 128>>>(Wih, Whh, bih, bhh, Wc1, bc1, Wc2, bc2, out);

    cudaStreamCaptureStatus cs = cudaStreamCaptureStatusNone;
    cudaStreamIsCapturing(cudaStreamPerThread, &cs);
    cudaEventDestroy(evF);
    cudaEventDestroy(evJ);
    if (cs == cudaStreamCaptureStatusNone) cudaStreamDestroy(s2);
}

// round 9
// speedup vs baseline: 1.1259x; 1.0121x over previous
#include <cuda_runtime.h>
#include <cuda_fp16.h>
#include <mma.h>
#include <math.h>

using namespace nvcuda;

#define T_ 6
#define N_ 20000
#define E_ 400000
#define F_ 64
#define C_ 64
#define H_ 128
#define BIG_ 0x3fffffff

// ---------------- scratch (device globals; no allocation) ----------------
__device__ __align__(128) int    g_lvl[T_][N_];
__device__ __align__(128) int    g_count[T_][N_];
__device__ __align__(128) int    g_rowptr[T_][N_ + 1];
__device__ __align__(128) int    g_cursor[T_][N_];
__device__ __align__(128) int    g_csrsrc[T_][E_];
__device__ __align__(128) float  g_dinv[T_][N_];
__device__ __align__(128) __half g_xh[T_][N_ * F_];   // half copy of x
__device__ __align__(128) __half g_w1h[F_ * H_];      // half copy of W1[0:64]
__device__ __align__(128) __half g_g1[T_][N_ * H_];   // g1 = dinv*(xl@W1), fp16
__device__ __align__(128) float  g_col[T_][N_];       // dinv*(h1 . W2[:,127])
__device__ unsigned long long    g_argmax[T_];
__device__ __align__(128) float  g_seq[T_ * H_];

// ---------------- init: lvl reset + seed + count zero + argmax zero ----------------
__global__ void k_init(const int* __restrict__ tgt) {
    int t = blockIdx.y;
    __shared__ int stgt[C_];
    if (threadIdx.x < C_) stgt[threadIdx.x] = tgt[t * C_ + threadIdx.x];
    __syncthreads();
    int i4 = (blockIdx.x * 256 + threadIdx.x) * 4;
    if (i4 < N_) {
        int4 v = make_int4(BIG_, BIG_, BIG_, BIG_);
#pragma unroll
        for (int j = 0; j < C_; j++) {
            int tg = stgt[j];
            if (tg == i4) v.x = 0;
            if (tg == i4 + 1) v.y = 0;
            if (tg == i4 + 2) v.z = 0;
            if (tg == i4 + 3) v.w = 0;
        }
        *(int4*)&g_lvl[t][i4] = v;
        *(int4*)&g_count[t][i4] = make_int4(0, 0, 0, 0);
    }
    if (blockIdx.x == 0 && threadIdx.x == 0) g_argmax[t] = 0ULL;
}

// ---------------- half conversions (fork branch; no BFS dependence) ----------------
__global__ void k_xhalf(const float* __restrict__ x) {
    int t = blockIdx.y;
    int i4 = (blockIdx.x * 256 + threadIdx.x) * 4;
    if (i4 >= N_ * F_) return;
    float4 v = *(const float4*)&x[(size_t)t * N_ * F_ + i4];
    __half2 p0 = __floats2half2_rn(v.x, v.y);
    __half2 p1 = __floats2half2_rn(v.z, v.w);
    *(uint2*)&g_xh[t][i4] = make_uint2(*(unsigned*)&p0, *(unsigned*)&p1);
}

__global__ void k_w1half(const float* __restrict__ W1) {
    for (int i = threadIdx.x * 2; i < F_ * H_; i += 512) {
        __half2 p = __floats2half2_rn(W1[i], W1[i + 1]);
        *(unsigned*)&g_w1h[i] = *(unsigned*)&p;
    }
}

// ---------------- BFS (level-stamped; writes during iter k are exactly k) ----------
__global__ void k_prop(const int* __restrict__ ei, int k) {
    int t = blockIdx.y;
    int i = blockIdx.x * blockDim.x + threadIdx.x;
    if (i >= E_) return;
    const int* src = ei + (size_t)t * 2 * E_;
    const int* dst = src + E_;
    int s = src[i], d = dst[i];
    int ls = g_lvl[t][s], ld = g_lvl[t][d];
    if (ls < k && ld > k) atomicMin(&g_lvl[t][d], k);
    if (ld < k && ls > k) atomicMin(&g_lvl[t][s], k);
}

// ---------------- CSR branch (FULL graph) ----------------
__global__ void k_count(const int* __restrict__ ei) {
    int t = blockIdx.y;
    int i = blockIdx.x * blockDim.x + threadIdx.x;
    if (i >= E_) return;
    const int* dst = ei + (size_t)t * 2 * E_ + E_;
    atomicAdd(&g_count[t][dst[i]], 1);
}

__global__ void k_scan() {
    int t = blockIdx.x;
    const int CH = 20;
    __shared__ int s[1024];
    int tid = threadIdx.x;
    int base = tid * CH;
    int loc[CH];
    int sum = 0;
#pragma unroll
    for (int i = 0; i < CH; i++) {
        int idx = base + i;
        int c = (idx < N_) ? g_count[t][idx] : 0;
        loc[i] = sum;
        sum += c;
    }
    s[tid] = sum;
    __syncthreads();
    for (int off = 1; off < 1024; off <<= 1) {
        int v = (tid >= off) ? s[tid - off] : 0;
        __syncthreads();
        s[tid] += v;
        __syncthreads();
    }
    int excl = s[tid] - sum;
#pragma unroll
    for (int i = 0; i < CH; i++) {
        int idx = base + i;
        if (idx < N_) {
            int o = excl + loc[i];
            g_rowptr[t][idx] = o;
            g_cursor[t][idx] = o;
        }
    }
    if (tid == 1023) g_rowptr[t][N_] = s[1023];
}

__global__ void k_fill(const int* __restrict__ ei) {
    int t = blockIdx.y;
    int i = blockIdx.x * blockDim.x + threadIdx.x;
    if (i >= E_) return;
    const int* src = ei + (size_t)t * 2 * E_;
    const int* dst = src + E_;
    int s = src[i], d = dst[i];
    int p = atomicAdd(&g_cursor[t][d], 1);
    g_csrsrc[t][p] = s;
}

// ---------------- join: subgraph degree + dinv ----------------
__global__ void __launch_bounds__(256) k_deg() {
    int t = blockIdx.y;
    int tid = threadIdx.x;
    int warp = tid >> 5, lane = tid & 31;
    int row = blockIdx.x * 8 + warp;
    if (row >= N_) return;
    const int* __restrict__ lvl = g_lvl[t];
    bool in = lvl[row] < BIG_;
    int cnt = 0;
    if (in) {
        int s0 = g_rowptr[t][row], s1 = g_rowptr[t][row + 1];
        const int* __restrict__ csr = g_csrsrc[t];
        for (int j = s0 + lane; j < s1; j += 32) cnt += (lvl[csr[j]] < BIG_) ? 1 : 0;
    }
    cnt += __shfl_down_sync(0xffffffffu, cnt, 16);
    cnt += __shfl_down_sync(0xffffffffu, cnt, 8);
    cnt += __shfl_down_sync(0xffffffffu, cnt, 4);
    cnt += __shfl_down_sync(0xffffffffu, cnt, 2);
    cnt += __shfl_down_sync(0xffffffffu, cnt, 1);
    if (lane == 0) g_dinv[t][row] = in ? rsqrtf((float)cnt + 1.0f) : 0.0f;
}

// ---------------- tensor-core GEMM: g1(half) = dinv * ([x,labels] @ W1) ------------
// 128x128 tile, 8 warps each own a 16-row strip, K=64 in 4 wmma steps.
// A tile (128x64 half, ldm 72) + W tile (64x128 half, ldm 128) in smem, loaded once.
// Epilogue staged via smem float buffer in two warp-groups (aliased over A/W).
#define BM2 128
#define A_LDM 72
#define STG_LDM 136
__global__ void __launch_bounds__(256) k_gemm(const float* __restrict__ W1) {
    extern __shared__ char smraw[];
    __half* Axs = (__half*)smraw;                       // [128][72]
    __half* W1s = (__half*)(smraw + BM2 * A_LDM * 2);   // [64][128]
    float* stg = (float*)smraw;                         // [4][16][136] (phase 2)

    int t = blockIdx.y;
    int tid = threadIdx.x;
    int warp = tid >> 5, lane = tid & 31;
    int m0 = blockIdx.x * BM2;
    const __half* __restrict__ xh = g_xh[t];

    // load A tile: 128 rows x 64 halfs = 1024 uint4
#pragma unroll
    for (int i = 0; i < 4; i++) {
        int e = tid + i * 256;
        int r = e >> 3, q = e & 7;
        int gr = m0 + r;
        uint4 v = make_uint4(0, 0, 0, 0);
        if (gr < N_) v = *(const uint4*)&xh[(size_t)gr * F_ + q * 8];
        *(uint4*)&Axs[r * A_LDM + q * 8] = v;
    }
    // load W tile: 64 x 128 halfs = 1024 uint4
#pragma unroll
    for (int i = 0; i < 4; i++) {
        int e = tid + i * 256;
        int r = e >> 4, q = e & 15;
        *(uint4*)&W1s[r * H_ + q * 8] = *(const uint4*)&g_w1h[r * H_ + q * 8];
    }
    __syncthreads();

    wmma::fragment<wmma::accumulator, 16, 16, 16, float> acc[8];
#pragma unroll
    for (int nt = 0; nt < 8; nt++) wmma::fill_fragment(acc[nt], 0.0f);

#pragma unroll
    for (int ks = 0; ks < 4; ks++) {
        wmma::fragment<wmma::matrix_a, 16, 16, 16, __half, wmma::row_major> af;
        wmma::load_matrix_sync(af, Axs + warp * 16 * A_LDM + ks * 16, A_LDM);
#pragma unroll
        for (int nt = 0; nt < 8; nt++) {
            wmma::fragment<wmma::matrix_b, 16, 16, 16, __half, wmma::row_major> bf;
            wmma::load_matrix_sync(bf, W1s + ks * 16 * H_ + nt * 16, H_);
            wmma::mma_sync(acc[nt], af, bf, acc[nt]);
        }
    }
    __syncthreads();  // A/W tiles dead; smem becomes staging

    // per-thread epilogue constants: cols lane*4..+3
    float w64[4], w65[4];
#pragma unroll
    for (int j = 0; j < 4; j++) {
        w64[j] = W1[(size_t)64 * H_ + lane * 4 + j];
        w65[j] = W1[(size_t)65 * H_ + lane * 4 + j];
    }

#pragma unroll
    for (int grp = 0; grp < 2; grp++) {
        bool mine = (warp >> 2) == grp;
        int wslot = warp & 3;
        if (mine) {
#pragma unroll
            for (int nt = 0; nt < 8; nt++)
                wmma::store_matrix_sync(stg + wslot * 16 * STG_LDM + nt * 16, acc[nt],
                                        STG_LDM, wmma::mem_row_major);
        }
        __syncthreads();
        if (mine) {
            for (int r = 0; r < 16; r++) {
                int gr = m0 + warp * 16 + r;
                if (gr >= N_) break;
                int lv = g_lvl[t][gr];
                float l0 = (lv == 0) ? 1.0f : 0.0f;
                float l1 = (lv > 0 && lv < BIG_) ? 1.0f : 0.0f;
                float d = g_dinv[t][gr];
                float e0 = d * (stg[wslot * 16 * STG_LDM + r * STG_LDM + lane * 4 + 0] + l0 * w64[0] + l1 * w65[0]);
                float e1 = d * (stg[wslot * 16 * STG_LDM + r * STG_LDM + lane * 4 + 1] + l0 * w64[1] + l1 * w65[1]);
                float e2 = d * (stg[wslot * 16 * STG_LDM + r * STG_LDM + lane * 4 + 2] + l0 * w64[2] + l1 * w65[2]);
                float e3 = d * (stg[wslot * 16 * STG_LDM + r * STG_LDM + lane * 4 + 3] + l0 * w64[3] + l1 * w65[3]);
                __half2 p0 = __floats2half2_rn(e0, e1);
                __half2 p1 = __floats2half2_rn(e2, e3);
                *(uint2*)&g_g1[t][(size_t)gr * H_ + lane * 4] =
                    make_uint2(*(unsigned*)&p0, *(unsigned*)&p1);
            }
        }
        __syncthreads();
    }
}

__device__ __forceinline__ float warp_sum(float v) {
    v += __shfl_down_sync(0xffffffffu, v, 16);
    v += __shfl_down_sync(0xffffffffu, v, 8);
    v += __shfl_down_sync(0xffffffffu, v, 4);
    v += __shfl_down_sync(0xffffffffu, v, 2);
    v += __shfl_down_sync(0xffffffffu, v, 1);
    return v;
}

// ---------------- SpMM1 over half g1 -> g_col only ----------------
__global__ void __launch_bounds__(256) k_spmm1(const float* __restrict__ b1,
                                               const float* __restrict__ W2) {
    int t = blockIdx.y;
    const __half* __restrict__ g = g_g1[t];

    __shared__ float w2c[H_];
    int tid = threadIdx.x;
    if (tid < H_) w2c[tid] = W2[(size_t)tid * H_ + (H_ - 1)];
    __syncthreads();

    int warp = tid >> 5, lane = tid & 31;
    int row = blockIdx.x * 8 + warp;
    if (row >= N_) return;

    int s0 = g_rowptr[t][row], s1 = g_rowptr[t][row + 1];
    const int* __restrict__ csr = g_csrsrc[t];
    int co = lane * 4;

    float ax = 0.f, ay = 0.f, az = 0.f, aw = 0.f;
    int j = s0;
    for (; j + 4 <= s1; j += 4) {
        int i0 = csr[j], i1 = csr[j + 1], i2 = csr[j + 2], i3 = csr[j + 3];
        uint2 r0 = *(const uint2*)&g[(size_t)i0 * H_ + co];
        uint2 r1 = *(const uint2*)&g[(size_t)i1 * H_ + co];
        uint2 r2 = *(const uint2*)&g[(size_t)i2 * H_ + co];
        uint2 r3 = *(const uint2*)&g[(size_t)i3 * H_ + co];
        float2 f;
        f = __half22float2(*(__half2*)&r0.x); ax += f.x; ay += f.y;
        f = __half22float2(*(__half2*)&r0.y); az += f.x; aw += f.y;
        f = __half22float2(*(__half2*)&r1.x); ax += f.x; ay += f.y;
        f = __half22float2(*(__half2*)&r1.y); az += f.x; aw += f.y;
        f = __half22float2(*(__half2*)&r2.x); ax += f.x; ay += f.y;
        f = __half22float2(*(__half2*)&r2.y); az += f.x; aw += f.y;
        f = __half22float2(*(__half2*)&r3.x); ax += f.x; ay += f.y;
        f = __half22float2(*(__half2*)&r3.y); az += f.x; aw += f.y;
    }
    for (; j < s1; j++) {
        uint2 r0 = *(const uint2*)&g[(size_t)csr[j] * H_ + co];
        float2 f;
        f = __half22float2(*(__half2*)&r0.x); ax += f.x; ay += f.y;
        f = __half22float2(*(__half2*)&r0.y); az += f.x; aw += f.y;
    }
    {
        uint2 r0 = *(const uint2*)&g[(size_t)row * H_ + co];
        float2 f;
        f = __half22float2(*(__half2*)&r0.x); ax += f.x; ay += f.y;
        f = __half22float2(*(__half2*)&r0.y); az += f.x; aw += f.y;
    }

    float d = g_dinv[t][row];
    float4 bb = *(const float4*)&b1[co];
    float h0 = fmaxf(fmaf(d, ax, bb.x), 0.f);
    float h1 = fmaxf(fmaf(d, ay, bb.y), 0.f);
    float h2 = fmaxf(fmaf(d, az, bb.z), 0.f);
    float h3 = fmaxf(fmaf(d, aw, bb.w), 0.f);

    float dot = h0 * w2c[co] + h1 * w2c[co + 1] + h2 * w2c[co + 2] + h3 * w2c[co + 3];
    dot = warp_sum(dot);
    if (lane == 0) g_col[t][row] = d * dot;
}

// ---------------- layer-2 scalar aggregation + fused argmax ----------------
__global__ void __launch_bounds__(256) k_col_argmax(const float* __restrict__ b2) {
    int t = blockIdx.y;
    int tid = threadIdx.x;
    int warp = tid >> 5, lane = tid & 31;
    int row = blockIdx.x * 8 + warp;
    unsigned long long p = 0ULL;
    float b = b2[H_ - 1];
    if (row < N_) {
        int s0 = g_rowptr[t][row], s1 = g_rowptr[t][row + 1];
        const int* __restrict__ csr = g_csrsrc[t];
        const float* __restrict__ col = g_col[t];
        float s = 0.f;
        for (int j = s0 + lane; j < s1; j += 32) s += col[csr[j]];
        s = warp_sum(s);
        if (lane == 0) {
            float d = g_dinv[t][row];
            if (d > 0.f) {
                float v = fmaxf(fmaf(d, s + col[row], b), 0.f);
                p = ((unsigned long long)__float_as_uint(v) << 32) |
                    (unsigned int)(0x7fffffff - row);
            }
        }
    }
    __shared__ unsigned long long sm[8];
    if (lane == 0) sm[warp] = p;
    __syncthreads();
    if (tid == 0) {
        unsigned long long m = sm[0];
#pragma unroll
        for (int i = 1; i < 8; i++) m = (sm[i] > m) ? sm[i] : m;
        if (m) atomicMax(&g_argmax[t], m);
    }
}

// ---------------- recompute h1 on top's nbhd; h2[top,:] -> g_seq ----------------
__global__ void __launch_bounds__(128) k_top(const float* __restrict__ b1,
                                             const float* __restrict__ W2,
                                             const float* __restrict__ b2) {
    int t = blockIdx.x;
    int top = 0x7fffffff - (int)(g_argmax[t] & 0x7fffffffULL);
    int c = threadIdx.x;
    __shared__ float svec[H_];
    const __half* __restrict__ g = g_g1[t];
    const int* __restrict__ csr = g_csrsrc[t];

    int s0 = g_rowptr[t][top], s1 = g_rowptr[t][top + 1];
    float sv = 0.f;
    float bc = b1[c];
    for (int idx = -1; idx < s1 - s0; idx++) {
        int u = (idx < 0) ? top : csr[s0 + idx];
        float du = g_dinv[t][u];
        if (du > 0.f) {
            int u0 = g_rowptr[t][u], u1 = g_rowptr[t][u + 1];
            float a0 = __half2float(g[(size_t)u * H_ + c]);
            float a1 = 0.f, a2 = 0.f, a3 = 0.f;
            int j = u0;
            for (; j + 4 <= u1; j += 4) {
                a0 += __half2float(g[(size_t)csr[j] * H_ + c]);
                a1 += __half2float(g[(size_t)csr[j + 1] * H_ + c]);
                a2 += __half2float(g[(size_t)csr[j + 2] * H_ + c]);
                a3 += __half2float(g[(size_t)csr[j + 3] * H_ + c]);
            }
            for (; j < u1; j++) a0 += __half2float(g[(size_t)csr[j] * H_ + c]);
            float agg = (a0 + a1) + (a2 + a3);
            float h = fmaxf(fmaf(du, agg, bc), 0.f);
            sv += du * h;
        }
    }
    svec[c] = sv;
    __syncthreads();

    float o = 0.f;
#pragma unroll 4
    for (int k = 0; k < H_; k++) o = fmaf(svec[k], W2[(size_t)k * H_ + c], o);
    float dtop = g_dinv[t][top];
    g_seq[t * H_ + c] = fmaxf(fmaf(dtop, o, b2[c]), 0.f);
}

// ---------------- GRU + MLP head ----------------
__global__ void __launch_bounds__(128) k_final(const float* __restrict__ Wih,
                                               const float* __restrict__ Whh,
                                               const float* __restrict__ bih,
                                               const float* __restrict__ bhh,
                                               const float* __restrict__ Wc1,
                                               const float* __restrict__ bc1,
                                               const float* __restrict__ Wc2,
                                               const float* __restrict__ bc2,
                                               float* __restrict__ out) {
    __shared__ float h[H_], xt[H_], sgi[3 * H_], sgh[3 * H_], hid[H_ / 2];
    int tid = threadIdx.x, lane = tid & 31, w = tid >> 5;
    h[tid] = 0.0f;
    __syncthreads();
    for (int t = 0; t < T_; t++) {
        xt[tid] = g_seq[t * H_ + tid];
        __syncthreads();
        for (int o = w; o < 3 * H_; o += 4) {
            float si = 0.f, sh = 0.f;
            for (int k = lane; k < H_; k += 32) {
                si += xt[k] * Wih[(size_t)o * H_ + k];
                sh += h[k] * Whh[(size_t)o * H_ + k];
            }
            si = warp_sum(si);
            sh = warp_sum(sh);
            if (lane == 0) {
                sgi[o] = si + bih[o];
                sgh[o] = sh + bhh[o];
            }
        }
        __syncthreads();
        float r = 1.0f / (1.0f + expf(-(sgi[tid] + sgh[tid])));
        float z = 1.0f / (1.0f + expf(-(sgi[tid + H_] + sgh[tid + H_])));
        float n = tanhf(sgi[tid + 2 * H_] + r * sgh[tid + 2 * H_]);
        float hn = (1.0f - z) * n + z * h[tid];
        __syncthreads();
        h[tid] = hn;
        __syncthreads();
    }
    if (tid < H_ / 2) {
        float s = bc1[tid];
        for (int k = 0; k < H_; k++) s += h[k] * Wc1[(size_t)k * (H_ / 2) + tid];
        hid[tid] = fmaxf(s, 0.0f);
    }
    __syncthreads();
    if (tid == 0) {
        float s = bc2[0];
        for (int j = 0; j < H_ / 2; j++) s += hid[j] * Wc2[j];
        out[0] = 1.0f / (1.0f + expf(-s));
    }
}

// ---------------- launch (fork-join) ----------------
extern "C" void kernel_launch(void* const* d_in, const int* in_sizes, int n_in,
                              void* d_out, int out_size) {
    const float* x   = (const float*)d_in[0];
    const int*   ei  = (const int*)d_in[1];
    const int*   tgt = (const int*)d_in[2];
    const float* W1  = (const float*)d_in[3];
    const float* b1  = (const float*)d_in[4];
    const float* W2  = (const float*)d_in[5];
    const float* b2  = (const float*)d_in[6];
    const float* Wih = (const float*)d_in[7];
    const float* Whh = (const float*)d_in[8];
    const float* bih = (const float*)d_in[9];
    const float* bhh = (const float*)d_in[10];
    const float* Wc1 = (const float*)d_in[11];
    const float* bc1 = (const float*)d_in[12];
    const float* Wc2 = (const float*)d_in[13];
    const float* bc2 = (const float*)d_in[14];
    float* out = (float*)d_out;

    const dim3 GRST((N_ / 4 + 255) / 256, T_);
    const dim3 GE((E_ + 255) / 256, T_);
    const dim3 GM((N_ + BM2 - 1) / BM2, T_);
    const dim3 GR((N_ + 7) / 8, T_);
    const dim3 GX((N_ * F_ / 4 + 255) / 256, T_);

    const int GEMM_SMEM = BM2 * A_LDM * 2 + F_ * H_ * 2;  // 34816 B (phase2 aliases)
    static int smem_set = 0;
    if (!smem_set) {
        cudaFuncSetAttribute(k_gemm, cudaFuncAttributeMaxDynamicSharedMemorySize, GEMM_SMEM);
        smem_set = 1;
    }

    cudaStream_t s2;
    cudaStreamCreateWithFlags(&s2, cudaStreamNonBlocking);
    cudaEvent_t evF, evJ;
    cudaEventCreateWithFlags(&evF, cudaEventDisableTiming);
    cudaEventCreateWithFlags(&evJ, cudaEventDisableTiming);

    k_init<<<GRST, 256>>>(tgt);               // lvl+seed+count+argmax init

    // fork: side stream: half conversions + full-graph CSR
    cudaEventRecord(evF, cudaStreamPerThread);
    cudaStreamWaitEvent(s2, evF, 0);
    k_xhalf<<<GX, 256, 0, s2>>>(x);
    k_w1half<<<1, 256, 0, s2>>>(W1);
    k_count<<<GE, 256, 0, s2>>>(ei);
    k_scan<<<T_, 1024, 0, s2>>>();
    k_fill<<<GE, 256, 0, s2>>>(ei);
    cudaEventRecord(evJ, s2);

    // main stream: BFS
    k_prop<<<GE, 256>>>(ei, 1);
    k_prop<<<GE, 256>>>(ei, 2);

    // join
    cudaStreamWaitEvent(cudaStreamPerThread, evJ, 0);
    k_deg<<<GR, 256>>>();
    k_gemm<<<GM, 256, GEMM_SMEM>>>(W1);
    k_spmm1<<<GR, 256>>>(b1, W2);
    k_col_argmax<<<GR, 256>>>(b2);
    k_top<<<T_, 128>>>(b1, W2, b2);
    k_final<<<1, 128>>>(Wih, Whh, bih, bhh, Wc1, bc1, Wc2, bc2, out);

    cudaStreamCaptureStatus cs = cudaStreamCaptureStatusNone;
    cudaStreamIsCapturing(cudaStreamPerThread, &cs);
    cudaEventDestroy(evF);
    cudaEventDestroy(evJ);
    if (cs == cudaStreamCaptureStatusNone) cudaStreamDestroy(s2);
}